// round 4
// baseline (speedup 1.0000x reference)
#include <cuda_runtime.h>
#include <cuda_bf16.h>
#include <stdint.h>

#define NNODES 8192
#define DIM    256
#define ALPHA  3.0f
#define NEG    0.2f

#define SM_TPB 512                    // softmax threads per block
#define CPT    (NNODES / SM_TPB)      // 16 values per thread
#define VEC4   (CPT / 4)              // 4 float4 chunks per thread

// Scratch (__device__ globals; no cudaMalloc allowed)
__device__ float        g_s1[NNODES];
__device__ float        g_s2p[NNODES];   // permuted: g_s2p[idx[j]] = s2[j]
__device__ unsigned int g_s2max_key;     // order-preserving uint encoding of max s2

// monotone float<->uint key (unsigned compare order == float order)
__device__ __forceinline__ unsigned int f2key(float f) {
    unsigned int b = __float_as_uint(f);
    return (b & 0x80000000u) ? ~b : (b | 0x80000000u);
}
__device__ __forceinline__ float key2f(unsigned int k) {
    return __uint_as_float((k & 0x80000000u) ? (k & 0x7fffffffu) : ~k);
}

__device__ __forceinline__ float fast_tanh_alpha(float v) {
    // tanh(ALPHA*v) = 1 - 2/(exp(2*ALPHA*v)+1); exact in both saturation limits
    float e = __expf(2.0f * ALPHA * v);
    return 1.0f - 2.0f * __frcp_rn(e + 1.0f);
}

// ---------------------------------------------------------------------------
// init: reset the atomic-max cell each call (determinism across graph replays)
// ---------------------------------------------------------------------------
__global__ void init_kernel() { g_s2max_key = 0u; }   // key 0 == most-negative float

// ---------------------------------------------------------------------------
// score: one WARP per node j (src = idx[j]); 8 dims per lane via 2x float4.
//   s1[j]        = tanh(a*e1[src,:]) . w[:D]
//   s2p[src]     = tanh(a*e2[src,:]) . w[D:]      (permuted scatter, 32KB)
//   g_s2max_key  = max over j (atomic)
// 256 threads = 8 warps/block, 1024 blocks, no __syncthreads in hot path.
// ---------------------------------------------------------------------------
__global__ void __launch_bounds__(256)
score_kernel(const int* __restrict__ idx,
             const float* __restrict__ e1,
             const float* __restrict__ e2,
             const float* __restrict__ w)
{
    const int warp = (blockIdx.x * 256 + threadIdx.x) >> 5;   // node j
    const int lane = threadIdx.x & 31;
    const int src  = idx[warp];

    const float4* r1 = (const float4*)(e1 + (size_t)src * DIM) + lane * 2;
    const float4* r2 = (const float4*)(e2 + (size_t)src * DIM) + lane * 2;
    const float4* w1 = (const float4*)(w)        + lane * 2;
    const float4* w2 = (const float4*)(w + DIM)  + lane * 2;

    float p1 = 0.f, p2 = 0.f;
    #pragma unroll
    for (int q = 0; q < 2; q++) {
        float4 a = r1[q], b = r2[q], wa = __ldg(&w1[q]), wb = __ldg(&w2[q]);
        p1 += fast_tanh_alpha(a.x) * wa.x + fast_tanh_alpha(a.y) * wa.y
            + fast_tanh_alpha(a.z) * wa.z + fast_tanh_alpha(a.w) * wa.w;
        p2 += fast_tanh_alpha(b.x) * wb.x + fast_tanh_alpha(b.y) * wb.y
            + fast_tanh_alpha(b.z) * wb.z + fast_tanh_alpha(b.w) * wb.w;
    }
    #pragma unroll
    for (int o = 16; o > 0; o >>= 1) {
        p1 += __shfl_down_sync(0xffffffffu, p1, o);
        p2 += __shfl_down_sync(0xffffffffu, p2, o);
    }
    if (lane == 0) {
        g_s1[warp] = p1;
        g_s2p[src] = p2;
        atomicMax(&g_s2max_key, f2key(p2));
    }
}

// ---------------------------------------------------------------------------
// softmax: one block per row i. 512 threads x 16 cols (4x float4).
//   row max is CLOSED FORM: m = leaky(s1[i] + b + s2max)   (leaky monotone)
//   single pass: e = exp(leaky(base + s2p[c]) - m), block-sum, float4 stores.
// Fully coalesced streaming stores; s2p (32KB) stays L1-resident.
// ---------------------------------------------------------------------------
__global__ void __launch_bounds__(SM_TPB, 4)
softmax_kernel(const float* __restrict__ att_b,
               float* __restrict__ out)
{
    const int i = blockIdx.x;
    const int t = threadIdx.x;

    const float base  = g_s1[i] + att_b[0];
    float       mx    = base + key2f(g_s2max_key);
    mx = (mx > 0.f) ? mx : NEG * mx;                 // exact row max

    const float4* s2p4 = (const float4*)g_s2p;

    float vals[CPT];
    float sum = 0.f;
    #pragma unroll
    for (int q = 0; q < VEC4; q++) {
        float4 s = __ldg(&s2p4[q * SM_TPB + t]);
        #pragma unroll
        for (int u = 0; u < 4; u++) {
            float x = base + ((const float*)&s)[u];
            x = (x > 0.f) ? x : NEG * x;
            float e = __expf(x - mx);
            vals[q * 4 + u] = e;
            sum += e;
        }
    }

    // block sum (16 warps)
    __shared__ float shs[SM_TPB / 32];
    #pragma unroll
    for (int o = 16; o > 0; o >>= 1)
        sum += __shfl_xor_sync(0xffffffffu, sum, o);
    if ((t & 31) == 0) shs[t >> 5] = sum;
    __syncthreads();
    sum = 0.f;
    #pragma unroll
    for (int wgi = 0; wgi < SM_TPB / 32; wgi++) sum += shs[wgi];

    const float inv = __frcp_rn(sum);

    float4* row4 = (float4*)(out + (size_t)i * NNODES);
    #pragma unroll
    for (int q = 0; q < VEC4; q++) {
        float4 v;
        v.x = vals[q * 4 + 0] * inv;
        v.y = vals[q * 4 + 1] * inv;
        v.z = vals[q * 4 + 2] * inv;
        v.w = vals[q * 4 + 3] * inv;
        __stcs(&row4[q * SM_TPB + t], v);            // streaming store hint
    }
}

// ---------------------------------------------------------------------------
// Inputs: idx[int32 N], emb1_w[f32 N*D], emb2_w[f32 N*D], att_w[f32 2D],
//         att_b[f32 1].  Output: f32 N*N.
// ---------------------------------------------------------------------------
extern "C" void kernel_launch(void* const* d_in, const int* in_sizes, int n_in,
                              void* d_out, int out_size)
{
    const int*   idx  = (const int*)  d_in[0];
    const float* e1   = (const float*)d_in[1];
    const float* e2   = (const float*)d_in[2];
    const float* attw = (const float*)d_in[3];
    const float* attb = (const float*)d_in[4];
    float*       out  = (float*)d_out;

    init_kernel<<<1, 1>>>();
    score_kernel<<<NNODES / 8, 256>>>(idx, e1, e2, attw);
    softmax_kernel<<<NNODES, SM_TPB>>>(attb, out);
}

// round 5
// speedup vs baseline: 1.7895x; 1.7895x over previous
#include <cuda_runtime.h>
#include <cuda_bf16.h>
#include <stdint.h>

#define NNODES 8192
#define DIM    256
#define ALPHA  3.0f
#define NEG    0.2f

#define TPB  256                    // softmax threads per block (R3-proven)
#define CPT  (NNODES / TPB)         // 32 values per thread
#define VEC4 (CPT / 4)              // 8 float4 chunks per thread

// Scratch (__device__ globals; no cudaMalloc allowed)
__device__ float g_s1[NNODES];
__device__ float g_s2p[NNODES];     // permuted: g_s2p[idx[j]] = s2[j]

__device__ __forceinline__ float fast_tanh_alpha(float v) {
    // tanh(ALPHA*v) = 1 - 2/(exp(2*ALPHA*v)+1); exact in both saturation limits
    float e = __expf(2.0f * ALPHA * v);
    return 1.0f - 2.0f * __frcp_rn(e + 1.0f);
}

// ---------------------------------------------------------------------------
// score: one WARP per node j (src = idx[j]); 8 dims per lane via 2x float4.
//   g_s1[j]    = tanh(a*e1[src,:]) . w[:D]
//   g_s2p[src] = tanh(a*e2[src,:]) . w[D:]     (permuted scatter, 32KB)
// 8 warps/block, 1024 blocks, no __syncthreads, no atomics.
// ---------------------------------------------------------------------------
__global__ void __launch_bounds__(256)
score_kernel(const int* __restrict__ idx,
             const float* __restrict__ e1,
             const float* __restrict__ e2,
             const float* __restrict__ w)
{
    const int warp = (blockIdx.x * 256 + threadIdx.x) >> 5;   // node j
    const int lane = threadIdx.x & 31;
    const int src  = idx[warp];

    const float4* r1 = (const float4*)(e1 + (size_t)src * DIM) + lane * 2;
    const float4* r2 = (const float4*)(e2 + (size_t)src * DIM) + lane * 2;
    const float4* w1 = (const float4*)(w)       + lane * 2;
    const float4* w2 = (const float4*)(w + DIM) + lane * 2;

    float p1 = 0.f, p2 = 0.f;
    #pragma unroll
    for (int q = 0; q < 2; q++) {
        float4 a = r1[q], b = r2[q], wa = __ldg(&w1[q]), wb = __ldg(&w2[q]);
        p1 += fast_tanh_alpha(a.x) * wa.x + fast_tanh_alpha(a.y) * wa.y
            + fast_tanh_alpha(a.z) * wa.z + fast_tanh_alpha(a.w) * wa.w;
        p2 += fast_tanh_alpha(b.x) * wb.x + fast_tanh_alpha(b.y) * wb.y
            + fast_tanh_alpha(b.z) * wb.z + fast_tanh_alpha(b.w) * wb.w;
    }
    #pragma unroll
    for (int o = 16; o > 0; o >>= 1) {
        p1 += __shfl_down_sync(0xffffffffu, p1, o);
        p2 += __shfl_down_sync(0xffffffffu, p2, o);
    }
    if (lane == 0) {
        g_s1[warp] = p1;
        g_s2p[src] = p2;
    }
}

// ---------------------------------------------------------------------------
// softmax: one block per row i. 256 threads x 32 cols (8x float4).
// NO max subtraction (softmax is shift-invariant; logits are small, so
// exp() is safely in fp32 range). Single pass:
//   e[c] = exp(leaky(s1[i] + b + s2p[c])), block-sum, then e*inv, float4 store.
// s2p (32KB) stays L1-resident across the ~55 rows each SM processes.
// ---------------------------------------------------------------------------
__global__ void __launch_bounds__(TPB)
softmax_kernel(const float* __restrict__ att_b,
               float* __restrict__ out)
{
    const int i = blockIdx.x;
    const int t = threadIdx.x;

    const float base = g_s1[i] + att_b[0];
    const float4* s2p4 = (const float4*)g_s2p;

    float vals[CPT];
    float sum = 0.f;
    #pragma unroll
    for (int q = 0; q < VEC4; q++) {
        float4 s = __ldg(&s2p4[q * TPB + t]);
        #pragma unroll
        for (int u = 0; u < 4; u++) {
            float x = base + ((const float*)&s)[u];
            x = (x > 0.f) ? x : NEG * x;      // leaky_relu
            float e = __expf(x);
            vals[q * 4 + u] = e;
            sum += e;
        }
    }

    // block sum (8 warps)
    __shared__ float shs[TPB / 32];
    #pragma unroll
    for (int o = 16; o > 0; o >>= 1)
        sum += __shfl_xor_sync(0xffffffffu, sum, o);
    if ((t & 31) == 0) shs[t >> 5] = sum;
    __syncthreads();
    sum = 0.f;
    #pragma unroll
    for (int wgi = 0; wgi < TPB / 32; wgi++) sum += shs[wgi];

    const float inv = __frcp_rn(sum);

    // contiguous float4 stores (plain, cached — no streaming hint)
    float4* row4 = (float4*)(out + (size_t)i * NNODES);
    #pragma unroll
    for (int q = 0; q < VEC4; q++) {
        float4 v;
        v.x = vals[q * 4 + 0] * inv;
        v.y = vals[q * 4 + 1] * inv;
        v.z = vals[q * 4 + 2] * inv;
        v.w = vals[q * 4 + 3] * inv;
        row4[q * TPB + t] = v;
    }
}

// ---------------------------------------------------------------------------
// Inputs: idx[int32 N], emb1_w[f32 N*D], emb2_w[f32 N*D], att_w[f32 2D],
//         att_b[f32 1].  Output: f32 N*N.
// ---------------------------------------------------------------------------
extern "C" void kernel_launch(void* const* d_in, const int* in_sizes, int n_in,
                              void* d_out, int out_size)
{
    const int*   idx  = (const int*)  d_in[0];
    const float* e1   = (const float*)d_in[1];
    const float* e2   = (const float*)d_in[2];
    const float* attw = (const float*)d_in[3];
    const float* attb = (const float*)d_in[4];
    float*       out  = (float*)d_out;

    score_kernel<<<NNODES / 8, 256>>>(idx, e1, e2, attw);
    softmax_kernel<<<NNODES, TPB>>>(attb, out);
}